// round 6
// baseline (speedup 1.0000x reference)
#include <cuda_runtime.h>
#include <cstdint>

#define NMS_B 8
#define NMS_N 10000
#define NMS_C 80
#define NMS_K 8
#define SCORE_THR 0.5f
#define NMS_NEG -1e9f
#define FNEGMAX -3.402823466e38f
#define TP_ROWS 64
#define N4 2500            // NMS_N / 4
#define NTHR 128           // nms block size (4 warps)

typedef unsigned long long u64;

// Scratch (allocation-free rule: __device__ globals)
__device__ float  g_scoresT[NMS_B * NMS_C * NMS_N];   // [B][C][N], raw scores
__device__ float  g_sel_score[NMS_B * NMS_C * NMS_K];
__device__ float4 g_sel_box  [NMS_B * NMS_C * NMS_K];
__device__ int    g_sel_valid[NMS_B * NMS_C * NMS_K];
__device__ int    g_done_count;

// key = (score_bits, N-n): max-key == (max score, lowest n). Scores > THR are
// positive floats (uint order == float order); below threshold -> 0 sentinel.
__device__ __forceinline__ u64 mkey(float v, int n) {
    return (v > SCORE_THR)
        ? ((((u64)__float_as_uint(v)) << 32) | (unsigned)(NMS_N - n))
        : 0ULL;
}

// ---------------------------------------------------------------------------
// Pass 1: vectorized transpose [B,N,C] -> [B,C,N]. Resets the ticket.
// ---------------------------------------------------------------------------
__global__ __launch_bounds__(256) void transpose_scores(
    const float* __restrict__ scores)
{
    __shared__ float t[TP_ROWS * 84];       // 84 = 21 float4 per row

    const int tid = threadIdx.x;
    const int n0  = blockIdx.x * TP_ROWS;
    const int b   = blockIdx.y;
    if (tid == 0 && n0 == 0 && b == 0) g_done_count = 0;

    const int nrows = min(TP_ROWS, NMS_N - n0);   // 64 or 16

    const float4* sp4 = reinterpret_cast<const float4*>(
        scores + ((size_t)b * NMS_N + n0) * NMS_C);
    float4* t4 = reinterpret_cast<float4*>(t);
    const int nin = nrows * 20;
    for (int i = tid; i < nin; i += 256) {
        int r = i / 20, c4 = i - r * 20;
        t4[r * 21 + c4] = __ldg(sp4 + i);
    }
    __syncthreads();

    const int nq  = nrows >> 2;
    const int sh  = (nrows == TP_ROWS) ? 4 : 2;
    const int msk = nq - 1;
    float4* op4 = reinterpret_cast<float4*>(g_scoresT)
                + (size_t)b * NMS_C * N4 + (n0 >> 2);
    const int nout = NMS_C * nq;
    for (int i = tid; i < nout; i += 256) {
        int c = i >> sh, n4 = i & msk;
        int n = n4 << 2;
        float4 v;
        v.x = t[(n + 0) * 84 + c];
        v.y = t[(n + 1) * 84 + c];
        v.z = t[(n + 2) * 84 + c];
        v.w = t[(n + 3) * 84 + c];
        op4[(size_t)c * N4 + n4] = v;
    }
}

// ---------------------------------------------------------------------------
// Pass 2: one 128-thread block per (batch, class). 128 chunks (chunk = idx4
// mod 128). The POP WARP is rotated per-block across SMSPs: pw = (bid/148)&3,
// so co-resident blocks' serial pop loops land on different schedulers.
// Pop-warp lane g holds chunks 4g..4g+3 as u64 keys IN REGISTERS.
// Last block (atomic ticket) runs the final per-batch top-8 inline.
// Output (f32): boxes[8][8][4] | scores[8][8] | classes[8][8] | valid[8]
// ---------------------------------------------------------------------------
__global__ __launch_bounds__(NTHR) void nms_per_class(
    const float* __restrict__ boxes, float* __restrict__ out)
{
    __shared__ float  s[NMS_N];           // 40 KB; reused as topk buffer
    __shared__ u64    cmax64[NTHR];
    __shared__ float4 selbox[NMS_K];
    __shared__ float  selsc[NMS_K];
    __shared__ int    sh_nsel;
    __shared__ int    sh_ticket;

    const int tid  = threadIdx.x;
    const int lane = tid & 31;
    const int blk  = blockIdx.x;
    const int b    = blk / NMS_C;
    const int c    = blk % NMS_C;
    const int pw   = (blk / 148) & 3;     // pop warp: spreads across SMSPs

    // ---- cooperative load: contiguous float4, threshold + u64 chunk keys ----
    const float4* sp4 = reinterpret_cast<const float4*>(g_scoresT)
                      + ((size_t)b * NMS_C + c) * N4;
    float4* s4 = reinterpret_cast<float4*>(s);
    u64 km = 0;
    #pragma unroll
    for (int k = 0; k < 20; k++) {                // 2500 = 19*128 + 68
        int idx4 = tid + (k << 7);
        if (idx4 < N4) {
            float4 v = __ldg(sp4 + idx4);
            float4 w;
            w.x = (v.x > SCORE_THR) ? v.x : NMS_NEG;
            w.y = (v.y > SCORE_THR) ? v.y : NMS_NEG;
            w.z = (v.z > SCORE_THR) ? v.z : NMS_NEG;
            w.w = (v.w > SCORE_THR) ? v.w : NMS_NEG;
            s4[idx4] = w;
            int n = idx4 << 2;
            u64 k0 = mkey(v.x, n);     if (k0 > km) km = k0;
            u64 k1 = mkey(v.y, n + 1); if (k1 > km) km = k1;
            u64 k2 = mkey(v.z, n + 2); if (k2 > km) km = k2;
            u64 k3 = mkey(v.w, n + 3); if (k3 > km) km = k3;
        }
    }
    cmax64[tid] = km;
    __syncthreads();

    // ---- pop warp: serial greedy NMS, register-resident chunk maxima ----
    if ((tid >> 5) == pw) {
        u64 c0 = cmax64[(lane << 2) + 0];
        u64 c1 = cmax64[(lane << 2) + 1];
        u64 c2 = cmax64[(lane << 2) + 2];
        u64 c3 = cmax64[(lane << 2) + 3];

        const float4* bxp = reinterpret_cast<const float4*>(boxes)
                          + (size_t)b * NMS_N;
        int    nsel = 0;
        float4 myb;
        float  mysc = 0.0f;
        bool   done = false;

        while (!done) {
            int npop = 0;
            for (int p = 0; p < NMS_K; p++) {
                // lane-local max of 4 regs, then 5-level u64 shfl-max
                u64 kk = c0;
                if (c1 > kk) kk = c1;
                if (c2 > kk) kk = c2;
                if (c3 > kk) kk = c3;
                #pragma unroll
                for (int off = 16; off > 0; off >>= 1) {
                    u64 ok = __shfl_down_sync(0xffffffffu, kk, off);
                    if (ok > kk) kk = ok;
                }
                kk = __shfl_sync(0xffffffffu, kk, 0);
                if ((unsigned)(kk >> 32) == 0u) break;   // exhausted
                int n = NMS_N - (int)(kk & 0xffffffffu);
                if (lane == p) {                          // record + prefetch box
                    mysc = __uint_as_float((unsigned)(kk >> 32));
                    myb  = __ldg(bxp + n);
                }
                if (lane == 0) s[n] = NMS_NEG;            // pop
                __syncwarp();

                // rescan the popped chunk (<=80 elems, 3 per lane)
                int owner = (n >> 2) & 127;
                int cnt   = ((owner < 68) ? 20 : 19) << 2;   // idx4=owner+128k<2500
                int nbase = owner << 2;
                u64 nk = 0;
                {
                    int e = lane;        // e = 4k + q -> n = nbase + 512k + q
                    int nn = nbase + ((e >> 2) << 9) + (e & 3);
                    nk = mkey(s[nn], nn);          // e<cnt always (cnt>=76)
                }
                {
                    int e = lane + 32;
                    int nn = nbase + ((e >> 2) << 9) + (e & 3);
                    u64 k2 = mkey(s[nn], nn);
                    if (k2 > nk) nk = k2;          // e<cnt always
                }
                {
                    int e = lane + 64;
                    if (e < cnt) {
                        int nn = nbase + ((e >> 2) << 9) + (e & 3);
                        u64 k2 = mkey(s[nn], nn);
                        if (k2 > nk) nk = k2;
                    }
                }
                #pragma unroll
                for (int off = 16; off > 0; off >>= 1) {
                    u64 ok = __shfl_down_sync(0xffffffffu, nk, off);
                    if (ok > nk) nk = ok;
                }
                nk = __shfl_sync(0xffffffffu, nk, 0);
                // predicated register update (no smem round-trip)
                int g = owner >> 2, slot = owner & 3;
                if (lane == g) {
                    if (slot == 0) c0 = nk;
                    else if (slot == 1) c1 = nk;
                    else if (slot == 2) c2 = nk;
                    else c3 = nk;
                }
                npop = p + 1;
            }
            __syncwarp();

            // IoU walk: candidate q (pop order) vs selected[], warp-parallel
            for (int q = 0; q < npop && nsel < NMS_K; q++) {
                float4 bb;
                bb.x = __shfl_sync(0xffffffffu, myb.x, q);
                bb.y = __shfl_sync(0xffffffffu, myb.y, q);
                bb.z = __shfl_sync(0xffffffffu, myb.z, q);
                bb.w = __shfl_sync(0xffffffffu, myb.w, q);
                float scq = __shfl_sync(0xffffffffu, mysc, q);
                bool sup = false;
                if (lane < nsel) {
                    float4 qq = selbox[lane];
                    float ih = fmaxf(fminf(bb.z, qq.z) - fmaxf(bb.x, qq.x), 0.0f);
                    float iw = fmaxf(fminf(bb.w, qq.w) - fmaxf(bb.y, qq.y), 0.0f);
                    float inter = ih * iw;
                    float uni = (bb.z - bb.x) * (bb.w - bb.y)
                              + (qq.z - qq.x) * (qq.w - qq.y) - inter;
                    sup = inter / fmaxf(uni, 1e-9f) > 0.5f;
                }
                if (!__ballot_sync(0xffffffffu, sup)) {
                    if (lane == 0) { selbox[nsel] = bb; selsc[nsel] = scq; }
                    nsel++;
                    __syncwarp();
                }
            }
            done = (nsel == NMS_K) || (npop < NMS_K);
        }
        if (lane == 0) sh_nsel = nsel;
    }
    __syncthreads();

    if (tid < NMS_K) {
        int o = blk * NMS_K + tid;
        int v = (tid < sh_nsel);
        g_sel_valid[o] = v;
        g_sel_score[o] = v ? selsc[tid] : NMS_NEG;
        float4 z = make_float4(0.f, 0.f, 0.f, 0.f);
        g_sel_box[o] = v ? selbox[tid] : z;
    }
    __threadfence();
    __syncthreads();
    if (tid == 0) sh_ticket = atomicAdd(&g_done_count, 1);
    __syncthreads();
    if (sh_ticket != NMS_B * NMS_C - 1) return;
    __threadfence();

    // ---- fused final top-8 (last block only): 4 warps x 2 batches each ----
    float* sc = s;
    const int warp = tid >> 5;
    for (int wb = warp; wb < NMS_B; wb += 4) {
        const int base = wb * NMS_C * NMS_K;
        for (int j2 = lane; j2 < NMS_C * NMS_K; j2 += 32)
            sc[wb * 640 + j2] = g_sel_score[base + j2];
        __syncwarp();

        int vcnt = 0;
        for (int k = 0; k < NMS_K; k++) {
            float bv = FNEGMAX; int bi = 1 << 30;
            #pragma unroll
            for (int q = 0; q < 20; q++) {            // 640 = 20*32
                int j2 = lane + (q << 5);
                float v = sc[wb * 640 + j2];
                if (v > bv || (v == bv && j2 < bi)) { bv = v; bi = j2; }
            }
            #pragma unroll
            for (int off = 16; off > 0; off >>= 1) {
                float ov = __shfl_down_sync(0xffffffffu, bv, off);
                int   oi = __shfl_down_sync(0xffffffffu, bi, off);
                if (ov > bv || (ov == bv && oi < bi)) { bv = ov; bi = oi; }
            }
            bi = __shfl_sync(0xffffffffu, bi, 0);
            bv = __shfl_sync(0xffffffffu, bv, 0);
            if (lane == 0) {
                sc[wb * 640 + bi] = FNEGMAX;
                int gi = base + bi;
                int valid = g_sel_valid[gi];
                float4 bb = g_sel_box[gi];
                float* ob = out + wb * 32 + k * 4;
                if (valid) {
                    ob[0] = fminf(fmaxf(bb.x, 0.f), 1.f);
                    ob[1] = fminf(fmaxf(bb.y, 0.f), 1.f);
                    ob[2] = fminf(fmaxf(bb.z, 0.f), 1.f);
                    ob[3] = fminf(fmaxf(bb.w, 0.f), 1.f);
                    out[NMS_B * 32 + wb * 8 + k] = bv;
                    out[NMS_B * 40 + wb * 8 + k] = (float)(bi >> 3);
                    vcnt++;
                } else {
                    ob[0] = ob[1] = ob[2] = ob[3] = 0.f;
                    out[NMS_B * 32 + wb * 8 + k] = 0.f;
                    out[NMS_B * 40 + wb * 8 + k] = 0.f;
                }
            }
            __syncwarp();
        }
        if (lane == 0) out[NMS_B * 48 + wb] = (float)vcnt;
    }
}

extern "C" void kernel_launch(void* const* d_in, const int* in_sizes, int n_in,
                              void* d_out, int out_size)
{
    const float* boxes  = (const float*)d_in[0];
    const float* scores = (const float*)d_in[1];
    if (n_in >= 2 && in_sizes[0] > in_sizes[1]) {   // defensive input order
        const float* t = boxes; boxes = scores; scores = t;
    }
    dim3 tg((NMS_N + TP_ROWS - 1) / TP_ROWS, NMS_B);
    transpose_scores<<<tg, 256>>>(scores);
    nms_per_class<<<NMS_B * NMS_C, NTHR>>>(boxes, (float*)d_out);
}